// round 16
// baseline (speedup 1.0000x reference)
#include <cuda_runtime.h>
#include <cuda_fp16.h>
#include <cstdint>

#define H       64
#define K       256
#define TILE_M  64
#define TPB     256
#define MARGIN  1.5f
#define BFS     144                      // f16 row stride in bytes
#define FLT_INF 3.402823466e+38f
#define QMAXP   512                      // queue entries per pair

// ---- dynamic smem layout (bytes) ----
#define OFF_CBF   0                      // B = f16(-2c): 256*144 = 36864
#define OFF_XBF   36864                  // X f16: 64*144 = 9216 -> 46080
#define OFF_C2    46080                  // ||c||^2 fp32 exact (pad 1024) -> 47104
#define OFF_C2P   47104                  // c2 packed f16x2: 128*4 -> 47616
#define OFF_RMIN  47616                  // 64 rows * 2 halves * 4B -> 48128
#define OFF_RES   48128                  // packed (d2,k): 64*8 -> 48640
#define OFF_Q     48640                  // 4 pairs * 512 * 4 -> 56832
#define OFF_QN    56832                  // 4 counters, 32B apart -> 56960
#define OFF_OFL   56960                  // 64*4 -> 57216
#define OFF_RCNT  57216                  // 64*4 -> 57472
#define OFF_RK1   57472                  // 64*4 -> 57728
#define SMEM_TOTAL 57728

#define PBAR(p) asm volatile("bar.sync %0, 64;" :: "r"((p) + 1) : "memory")

__device__ __forceinline__ uint32_t smem_u32(const void* p) {
    uint32_t a;
    asm("{ .reg .u64 t; cvta.to.shared.u64 t, %1; cvt.u32.u64 %0, t; }" : "=r"(a) : "l"(p));
    return a;
}

__device__ __forceinline__ uint32_t f16x2_pack(float lo, float hi) {
    __half2 h = __floats2half2_rn(lo, hi);
    return *(uint32_t*)&h;
}

__device__ __forceinline__ void ldsm4(uint32_t* r, uint32_t addr) {
    asm volatile("ldmatrix.sync.aligned.m8n8.x4.shared.b16 {%0,%1,%2,%3}, [%4];"
        : "=r"(r[0]), "=r"(r[1]), "=r"(r[2]), "=r"(r[3]) : "r"(addr));
}

// f16 in, f16 acc: d0 = row g cols{k0,k0+1}, d1 = row g+8 same cols
__device__ __forceinline__ void mma_f16(uint32_t& d0, uint32_t& d1,
                                        const uint32_t* a, const uint32_t* b) {
    asm volatile("mma.sync.aligned.m16n8k16.row.col.f16.f16.f16.f16 "
        "{%0,%1}, {%2,%3,%4,%5}, {%6,%7}, {%0,%1};"
        : "+r"(d0), "+r"(d1)
        : "r"(a[0]), "r"(a[1]), "r"(a[2]), "r"(a[3]), "r"(b[0]), "r"(b[1]));
}

// exact rescore (sequential-h fp32, float4 loads from gmem), monotone-packed (d2,k)
__device__ __forceinline__ unsigned long long rescore_pack(const float* __restrict__ xr,
                                                           const float* __restrict__ crow,
                                                           float c2k, int k) {
    float x2 = 0.f, dot = 0.f;
    #pragma unroll
    for (int h4 = 0; h4 < H / 4; ++h4) {
        float4 xv = __ldg((const float4*)(xr + h4 * 4));
        float4 cv = __ldg((const float4*)(crow + h4 * 4));
        x2 = __fadd_rn(x2, __fmul_rn(xv.x, xv.x));
        dot = __fmaf_rn(xv.x, cv.x, dot);
        x2 = __fadd_rn(x2, __fmul_rn(xv.y, xv.y));
        dot = __fmaf_rn(xv.y, cv.y, dot);
        x2 = __fadd_rn(x2, __fmul_rn(xv.z, xv.z));
        dot = __fmaf_rn(xv.z, cv.z, dot);
        x2 = __fadd_rn(x2, __fmul_rn(xv.w, xv.w));
        dot = __fmaf_rn(xv.w, cv.w, dot);
    }
    float d2 = __fmaf_rn(-2.f, dot, __fadd_rn(x2, c2k));
    uint32_t b = __float_as_uint(d2);
    b ^= (b & 0x80000000u) ? 0xFFFFFFFFu : 0x80000000u;    // monotone map
    return ((unsigned long long)b << 32) | (unsigned)k;
}

extern __shared__ char smem_raw[];

__global__ __launch_bounds__(TPB, 3)
void LatentSpaceClustering_46797963657837_kernel(const float* __restrict__ x,
                                                 const float* __restrict__ c,
                                                 float* __restrict__ out,
                                                 int n, int num_tiles) {
    const uint32_t sbase = smem_u32(smem_raw);
    float*    c2f  = (float*)(smem_raw + OFF_C2);
    uint32_t* c2p  = (uint32_t*)(smem_raw + OFF_C2P);
    float*    rmin = (float*)(smem_raw + OFF_RMIN);
    unsigned long long* res = (unsigned long long*)(smem_raw + OFF_RES);
    int* ofl  = (int*)(smem_raw + OFF_OFL);
    int* rcnt = (int*)(smem_raw + OFF_RCNT);
    int* rk1  = (int*)(smem_raw + OFF_RK1);
    const int tid = threadIdx.x;
    const int lane = tid & 31, w = tid >> 5;
    const int groupID = lane >> 2, tig = lane & 3;
    const int pr = w & 3, half = w >> 2;            // pair id, n-half
    const int pairtid = half * 32 + lane;           // 0..63 within pair
    const int hbase = half * 128;

    uint32_t* qp  = (uint32_t*)(smem_raw + OFF_Q) + pr * QMAXP;
    int*      qnp = (int*)(smem_raw + OFF_QN + pr * 32);

    // ---- stage B = f16(-2c) (padded rows) ----
    {
        const float4* c4 = (const float4*)c;
        for (int j = tid; j < K * H / 4; j += TPB) {
            float4 v = c4[j];
            int k = j >> 4, h = (j & 15) << 2;
            uint2 p = make_uint2(f16x2_pack(-2.f * v.x, -2.f * v.y),
                                 f16x2_pack(-2.f * v.z, -2.f * v.w));
            *(uint2*)(smem_raw + OFF_CBF + k * BFS + h * 2) = p;
        }
    }
    // ---- exact ||c_k||^2 (fp32 sequential, reference-style) ----
    {
        int k = tid;                                // TPB == K
        const float* cr = c + k * H;
        float s = 0.f;
        #pragma unroll 8
        for (int h = 0; h < H; ++h) {
            float v = __ldg(cr + h);
            s = __fadd_rn(s, __fmul_rn(v, v));
        }
        c2f[k] = s;
    }
    __syncthreads();
    if (tid < 128) c2p[tid] = f16x2_pack(c2f[2 * tid], c2f[2 * tid + 1]);
    __syncthreads();

    const uint32_t a_base = sbase + OFF_XBF + (pr * 16 + (lane & 15)) * BFS + ((lane >> 4) * 16);
    const uint32_t b_base = sbase + OFF_CBF
        + (hbase + (lane & 7) + ((lane >> 4) << 3)) * BFS
        + (((lane >> 3) & 1) * 16);
    const int r0 = pr * 16 + groupID, r1 = r0 + 8;  // CTA-tile rows for this thread

    for (int tile = blockIdx.x; tile < num_tiles; tile += gridDim.x) {
        const long long pbase = (long long)tile * TILE_M + pr * 16;

        // ---- stage X: LDG fp32 -> cvt -> STS f16 (pair's 16 rows); init state ----
        #pragma unroll
        for (int i = 0; i < 4; ++i) {
            int chunk = i * 64 + pairtid;           // 256 chunks (16 rows * 16 f4)
            int row = chunk >> 4, h4 = chunk & 15;
            float4 v = make_float4(0.f, 0.f, 0.f, 0.f);
            if (pbase + row < n)
                v = __ldg((const float4*)(x + (pbase + row) * H + h4 * 4));
            uint2 p = make_uint2(f16x2_pack(v.x, v.y), f16x2_pack(v.z, v.w));
            *(uint2*)(smem_raw + OFF_XBF + (pr * 16 + row) * BFS + h4 * 8) = p;
        }
        if (pairtid < 16) {
            int rg = pr * 16 + pairtid;
            res[rg] = 0xFFFFFFFFFFFFFFFFull;
            ofl[rg] = 0;
            rcnt[rg] = 0;
        }
        if (pairtid == 16) *qnp = 0;
        PBAR(pr);

        // ---- mma: acc(f16x2) init = c2; B = -2c => acc = c2 - 2 x.c ----
        uint32_t accA[16], accB[16];                 // row r0, row r1; 2 k each
        #pragma unroll
        for (int j = 0; j < 16; ++j) {
            uint32_t cv = c2p[hbase / 2 + j * 4 + tig];
            accA[j] = cv; accB[j] = cv;
        }
        uint32_t aa[2][4];                           // A double-buffered per k-step
        uint32_t bb[2][4];
        ldsm4(aa[0], a_base);
        ldsm4(bb[0], b_base);
        #pragma unroll
        for (int it = 0; it < 32; ++it) {            // it = ks*8 + jp
            int cur = it & 1;
            if (it < 31) {
                int nx = it + 1;
                ldsm4(bb[cur ^ 1], b_base + (nx & 7) * (16 * BFS) + (nx >> 3) * 32);
                if ((nx & 7) == 0)                   // next k-step's A -> OTHER buffer
                    ldsm4(aa[(nx >> 3) & 1], a_base + (nx >> 3) * 32);
            }
            int jp = it & 7;
            const uint32_t* a = aa[(it >> 3) & 1];   // current k-step's buffer
            mma_f16(accA[jp * 2],     accB[jp * 2],     a, bb[cur]);
            mma_f16(accA[jp * 2 + 1], accB[jp * 2 + 1], a, bb[cur] + 2);
        }

        // ---- per-row min via packed hmin2 ----
        __half2 hA = *(__half2*)&accA[0], hB = *(__half2*)&accB[0];
        #pragma unroll
        for (int j = 1; j < 16; ++j) {
            hA = __hmin2(hA, *(__half2*)&accA[j]);
            hB = __hmin2(hB, *(__half2*)&accB[j]);
        }
        float mn0 = fminf(__low2float(hA), __high2float(hA));
        float mn1 = fminf(__low2float(hB), __high2float(hB));
        #pragma unroll
        for (int off = 1; off <= 2; off <<= 1) {
            mn0 = fminf(mn0, __shfl_xor_sync(0xffffffffu, mn0, off));
            mn1 = fminf(mn1, __shfl_xor_sync(0xffffffffu, mn1, off));
        }
        if (tig == 0) { rmin[r0 * 2 + half] = mn0; rmin[r1 * 2 + half] = mn1; }
        PBAR(pr);

        // ---- screen: packed compares, push hits to pair queue ----
        const float thr0 = fminf(rmin[r0 * 2], rmin[r0 * 2 + 1]) + MARGIN;
        const float thr1 = fminf(rmin[r1 * 2], rmin[r1 * 2 + 1]) + MARGIN;
        const __half2 t0 = __float2half2_rn(thr0);
        const __half2 t1 = __float2half2_rn(thr1);
        #pragma unroll
        for (int j = 0; j < 16; ++j) {
            int k0 = hbase + j * 8 + tig * 2;
            __half2 cA = __hlt2(*(__half2*)&accA[j], t0);
            uint32_t mA = *(uint32_t*)&cA;
            if (mA) {
                if (mA & 0xFFFFu) {
                    atomicAdd(&rcnt[r0], 1); rk1[r0] = k0;
                    int idx = atomicAdd(qnp, 1);
                    if (idx < QMAXP) qp[idx] = ((uint32_t)groupID << 8) | (uint32_t)k0;
                    else ofl[r0] = 1;
                }
                if (mA >> 16) {
                    atomicAdd(&rcnt[r0], 1); rk1[r0] = k0 + 1;
                    int idx = atomicAdd(qnp, 1);
                    if (idx < QMAXP) qp[idx] = ((uint32_t)groupID << 8) | (uint32_t)(k0 + 1);
                    else ofl[r0] = 1;
                }
            }
            __half2 cB = __hlt2(*(__half2*)&accB[j], t1);
            uint32_t mB = *(uint32_t*)&cB;
            if (mB) {
                if (mB & 0xFFFFu) {
                    atomicAdd(&rcnt[r1], 1); rk1[r1] = k0;
                    int idx = atomicAdd(qnp, 1);
                    if (idx < QMAXP) qp[idx] = ((uint32_t)(groupID + 8) << 8) | (uint32_t)k0;
                    else ofl[r1] = 1;
                }
                if (mB >> 16) {
                    atomicAdd(&rcnt[r1], 1); rk1[r1] = k0 + 1;
                    int idx = atomicAdd(qnp, 1);
                    if (idx < QMAXP) qp[idx] = ((uint32_t)(groupID + 8) << 8) | (uint32_t)(k0 + 1);
                    else ofl[r1] = 1;
                }
            }
        }
        PBAR(pr);

        // ---- single-candidate fast path ----
        if (pairtid < 16) {
            int rg = pr * 16 + pairtid;
            if (rcnt[rg] == 1) res[rg] = (unsigned)rk1[rg];
        }
        // ---- pair-parallel exact rescore for multi-candidate rows ----
        {
            int total = *qnp;
            if (total > QMAXP) total = QMAXP;
            for (int i = pairtid; i < total; i += 64) {
                uint32_t e = qp[i];
                int rl = e >> 8, k = e & 255;
                int rg = pr * 16 + rl;
                if (rcnt[rg] > 1 && pbase + rl < n)
                    atomicMin(&res[rg],
                              rescore_pack(x + (size_t)(pbase + rl) * H,
                                           c + (size_t)k * H, c2f[k], k));
            }
        }
        // overflow fallback (pathological only)
        if (pairtid < 16) {
            int rg = pr * 16 + pairtid;
            if (ofl[rg] && pbase + pairtid < n) {
                for (int k = 0; k < K; ++k)
                    atomicMin(&res[rg],
                              rescore_pack(x + (size_t)(pbase + pairtid) * H,
                                           c + (size_t)k * H, c2f[k], k));
            }
        }
        PBAR(pr);

        // ---- write back (pair rows) ----
        if (pairtid < 16) {
            long long g = pbase + pairtid;
            if (g < n) out[g] = (float)(uint32_t)(res[pr * 16 + pairtid] & 0xFFFFFFFFull);
        }
    }
}

extern "C" void kernel_launch(void* const* d_in, const int* in_sizes, int n_in,
                              void* d_out, int out_size) {
    const float* x = (const float*)d_in[0];
    const float* c = (const float*)d_in[1];
    int n = in_sizes[0] / H;
    int num_tiles = (n + TILE_M - 1) / TILE_M;

    int sms = 148;
    cudaDeviceGetAttribute(&sms, cudaDevAttrMultiProcessorCount, 0);

    cudaFuncSetAttribute(LatentSpaceClustering_46797963657837_kernel,
                         cudaFuncAttributeMaxDynamicSharedMemorySize, SMEM_TOTAL);

    int grid = 3 * sms;
    if (grid > num_tiles) grid = num_tiles;
    LatentSpaceClustering_46797963657837_kernel<<<grid, TPB, SMEM_TOTAL>>>(
        x, c, (float*)d_out, n, num_tiles);
}